// round 15
// baseline (speedup 1.0000x reference)
#include <cuda_runtime.h>
#include <cuda_bf16.h>
#include <mma.h>
#include <cstdint>

using namespace nvcuda;

// ---------------------------------------------------------------------------
// GCN 4-layer forward on GB300 (sm_103a).
// R14: R12 skeleton; GEMM1 + GEMM2 via wmma bf16x3 (HMMA tensor path,
// hi/lo split of both operands, 3 accumulating mma_sync per k-frag).
// tcgen05 is unavailable (harness targets sm_103, not sm_103a).
// ---------------------------------------------------------------------------

#define MAX_N 100000
#define MAX_E 800000
#define MAX_G 500

__device__ float g_norm_out[MAX_N];
__device__ float g_norm_in[MAX_N];
__device__ int   g_deg_out[MAX_N];
__device__ int   g_deg_in[MAX_N];
__device__ int   g_row_ptr[MAX_N + 1];
__device__ int   g_cursor[MAX_N];
__device__ int   g_csr_src[MAX_E];
__device__ float g_h0[MAX_N * 128];
__device__ float g_h1[MAX_N * 64];
__device__ float g_gsum[MAX_G * 4];
__device__ int   g_bsum[32];
__device__ int   g_sync[4];

// Device-wide barrier: all blocks co-resident (148 blocks, 1/SM).
__device__ __forceinline__ void gbar(int idx, int nb) {
    __syncthreads();
    if (threadIdx.x == 0) {
        __threadfence();
        atomicAdd(&g_sync[idx], 1);
        while (atomicAdd(&g_sync[idx], 0) < nb) { }
    }
    __syncthreads();
}

// ---------------------------------------------------------------------------
// Persistent preprocessing: degrees -> scan(+norms) -> csr_fill (R12 verbatim).
// ---------------------------------------------------------------------------
__global__ void __launch_bounds__(1024, 1)
prep_kernel(const int* __restrict__ src, const int* __restrict__ dst,
            int n, int e, int nsb) {
    const int NBK = gridDim.x;
    int b = blockIdx.x, t = threadIdx.x, lane = t & 31, w = t >> 5;
    int gtid = b * 1024 + t;
    int gsz = NBK * 1024;

    for (int i = gtid; i < e; i += gsz) {
        atomicAdd(&g_deg_out[src[i]], 1);
        atomicAdd(&g_deg_in[dst[i]], 1);
    }
    gbar(0, NBK);

    __shared__ int swarp[32];
    __shared__ int s_boff;
    int4 v = make_int4(0, 0, 0, 0);
    int s = 0, ts = 0;
    int i0 = b * 4096 + t * 4;
    if (b < nsb) {
        if (i0 + 3 < n) v = *(const int4*)&g_deg_in[i0];
        else {
            if (i0     < n) v.x = g_deg_in[i0];
            if (i0 + 1 < n) v.y = g_deg_in[i0 + 1];
            if (i0 + 2 < n) v.z = g_deg_in[i0 + 2];
            if (i0 + 3 < n) v.w = g_deg_in[i0 + 3];
        }
        if (i0 < n) {
            g_norm_in[i0] = rsqrtf(fmaxf((float)v.x, 1.f));
            g_norm_out[i0] = rsqrtf(fmaxf((float)g_deg_out[i0], 1.f));
        }
        if (i0 + 1 < n) {
            g_norm_in[i0 + 1] = rsqrtf(fmaxf((float)v.y, 1.f));
            g_norm_out[i0 + 1] = rsqrtf(fmaxf((float)g_deg_out[i0 + 1], 1.f));
        }
        if (i0 + 2 < n) {
            g_norm_in[i0 + 2] = rsqrtf(fmaxf((float)v.z, 1.f));
            g_norm_out[i0 + 2] = rsqrtf(fmaxf((float)g_deg_out[i0 + 2], 1.f));
        }
        if (i0 + 3 < n) {
            g_norm_in[i0 + 3] = rsqrtf(fmaxf((float)v.w, 1.f));
            g_norm_out[i0 + 3] = rsqrtf(fmaxf((float)g_deg_out[i0 + 3], 1.f));
        }
        ts = v.x + v.y + v.z + v.w;
        s = ts;
        #pragma unroll
        for (int o = 1; o < 32; o <<= 1) {
            int x = __shfl_up_sync(0xffffffffu, s, o);
            if (lane >= o) s += x;
        }
        if (lane == 31) swarp[w] = s;
        __syncthreads();
        if (w == 0) {
            int ws = swarp[lane];
            #pragma unroll
            for (int o = 1; o < 32; o <<= 1) {
                int x = __shfl_up_sync(0xffffffffu, ws, o);
                if (lane >= o) ws += x;
            }
            swarp[lane] = ws;
        }
        __syncthreads();
        if (t == 0) g_bsum[b] = swarp[31];
    }
    gbar(1, NBK);

    if (b < nsb) {
        if (w == 0) {
            int acc = (lane < b) ? g_bsum[lane] : 0;
            #pragma unroll
            for (int o = 16; o; o >>= 1) acc += __shfl_down_sync(0xffffffffu, acc, o);
            if (lane == 0) {
                s_boff = acc;
                if (b == nsb - 1) g_row_ptr[n] = acc + swarp[31];
            }
        }
        __syncthreads();
        int pre = (w > 0) ? swarp[w - 1] : 0;
        int e0 = s_boff + pre + s - ts;
        int e1 = e0 + v.x, e2 = e1 + v.y, e3 = e2 + v.z;
        if (i0     < n) { g_row_ptr[i0]     = e0; g_cursor[i0]     = e0; }
        if (i0 + 1 < n) { g_row_ptr[i0 + 1] = e1; g_cursor[i0 + 1] = e1; }
        if (i0 + 2 < n) { g_row_ptr[i0 + 2] = e2; g_cursor[i0 + 2] = e2; }
        if (i0 + 3 < n) { g_row_ptr[i0 + 3] = e3; g_cursor[i0 + 3] = e3; }
    }
    gbar(2, NBK);

    for (int i = gtid; i < e; i += gsz) {
        int p = atomicAdd(&g_cursor[dst[i]], 1);
        g_csr_src[p] = src[i];
    }
}

// ---------------------------------------------------------------------------
// Gather-aggregate DIM=64: warp/node, 8-way MLP unroll (R12 verbatim).
// ---------------------------------------------------------------------------
template<bool RELU, bool HASB, bool SRCSCALE>
__global__ void agg64_kernel(const float* __restrict__ hin,
                             float* __restrict__ hout,
                             const float* __restrict__ bias, int n) {
    int node = (blockIdx.x * blockDim.x + threadIdx.x) >> 5;
    int l = threadIdx.x & 31;
    if (node >= n) return;
    int beg = g_row_ptr[node];
    int end = g_row_ptr[node + 1];
    float ni = g_norm_in[node];
    const float* base = hin + l * 2;
    float2 a0 = {0,0}, a1 = {0,0}, a2 = {0,0}, a3 = {0,0};
    float2 a4 = {0,0}, a5 = {0,0}, a6 = {0,0}, a7 = {0,0};
    int e = beg;
    for (; e + 7 < end; e += 8) {
        int s0 = g_csr_src[e],     s1 = g_csr_src[e + 1];
        int s2 = g_csr_src[e + 2], s3 = g_csr_src[e + 3];
        int s4 = g_csr_src[e + 4], s5 = g_csr_src[e + 5];
        int s6 = g_csr_src[e + 6], s7 = g_csr_src[e + 7];
        float2 v0 = *(const float2*)(base + s0 * 64);
        float2 v1 = *(const float2*)(base + s1 * 64);
        float2 v2 = *(const float2*)(base + s2 * 64);
        float2 v3 = *(const float2*)(base + s3 * 64);
        float2 v4 = *(const float2*)(base + s4 * 64);
        float2 v5 = *(const float2*)(base + s5 * 64);
        float2 v6 = *(const float2*)(base + s6 * 64);
        float2 v7 = *(const float2*)(base + s7 * 64);
        if (SRCSCALE) {
            float n0 = g_norm_out[s0], n1 = g_norm_out[s1];
            float n2 = g_norm_out[s2], n3 = g_norm_out[s3];
            float n4 = g_norm_out[s4], n5 = g_norm_out[s5];
            float n6 = g_norm_out[s6], n7 = g_norm_out[s7];
            a0.x = fmaf(v0.x, n0, a0.x); a0.y = fmaf(v0.y, n0, a0.y);
            a1.x = fmaf(v1.x, n1, a1.x); a1.y = fmaf(v1.y, n1, a1.y);
            a2.x = fmaf(v2.x, n2, a2.x); a2.y = fmaf(v2.y, n2, a2.y);
            a3.x = fmaf(v3.x, n3, a3.x); a3.y = fmaf(v3.y, n3, a3.y);
            a4.x = fmaf(v4.x, n4, a4.x); a4.y = fmaf(v4.y, n4, a4.y);
            a5.x = fmaf(v5.x, n5, a5.x); a5.y = fmaf(v5.y, n5, a5.y);
            a6.x = fmaf(v6.x, n6, a6.x); a6.y = fmaf(v6.y, n6, a6.y);
            a7.x = fmaf(v7.x, n7, a7.x); a7.y = fmaf(v7.y, n7, a7.y);
        } else {
            a0.x += v0.x; a0.y += v0.y; a1.x += v1.x; a1.y += v1.y;
            a2.x += v2.x; a2.y += v2.y; a3.x += v3.x; a3.y += v3.y;
            a4.x += v4.x; a4.y += v4.y; a5.x += v5.x; a5.y += v5.y;
            a6.x += v6.x; a6.y += v6.y; a7.x += v7.x; a7.y += v7.y;
        }
    }
    for (; e < end; e++) {
        int s0 = g_csr_src[e];
        float2 v = *(const float2*)(base + s0 * 64);
        if (SRCSCALE) {
            float n0 = g_norm_out[s0];
            a0.x = fmaf(v.x, n0, a0.x); a0.y = fmaf(v.y, n0, a0.y);
        } else { a0.x += v.x; a0.y += v.y; }
    }
    float ax = ((a0.x + a1.x) + (a2.x + a3.x)) + ((a4.x + a5.x) + (a6.x + a7.x));
    float ay = ((a0.y + a1.y) + (a2.y + a3.y)) + ((a4.y + a5.y) + (a6.y + a7.y));
    ax *= ni; ay *= ni;
    if (HASB) { ax += bias[l * 2]; ay += bias[l * 2 + 1]; }
    if (RELU) { ax = fmaxf(ax, 0.0f); ay = fmaxf(ay, 0.0f); }
    float2 o; o.x = ax; o.y = ay;
    *(float2*)&hout[node * 64 + l * 2] = o;
}

// ---------------------------------------------------------------------------
// wmma bf16x3 GEMM: out[N,M] = op(in[N,K] @ W[K,M]), fp32 accumulate.
// Both operands split hi/lo bf16; acc += Ah*Bh + Ah*Bl + Al*Bh.
// Block: 256 thr (8 warps), tile 64 rows x M cols; warp owns TPW 16x16 tiles.
// ---------------------------------------------------------------------------
template<int K, int M, bool RELU, bool BIAS, bool RSCALE>
__global__ void __launch_bounds__(256, 2)
gemm_wmma_kernel(const float* __restrict__ in, const float* __restrict__ W,
                 const float* __restrict__ bias, float* __restrict__ out, int n) {
    constexpr int THREADS = 256;
    constexpr int RT = 64;               // rows per tile
    constexpr int SA = K + 8;            // A smem stride (elements)
    constexpr int KT = K / 16;           // k-fragments
    constexpr int CT = M / 16;           // col tiles
    constexpr int TILES = (RT / 16) * CT;
    constexpr int TPW = TILES / 8;       // tiles per warp
    constexpr int KV = K / 4;

    extern __shared__ char smx[];
    __nv_bfloat16* sAh = (__nv_bfloat16*)smx;                       // RT*SA
    __nv_bfloat16* sAl = sAh + RT * SA;
    __nv_bfloat16* sBh = sAl + RT * SA;                             // K*M
    __nv_bfloat16* sBl = sBh + K * M;
    float* sOut = (float*)(sBl + K * M);                            // RT*M
    float* sBias = sOut + RT * M;                                   // M

    const int tid = threadIdx.x;
    const int wid = tid >> 5;

    // Stage W hi/lo (once).
    for (int idx = tid; idx < K * M / 4; idx += THREADS) {
        float4 wv = ((const float4*)W)[idx];
        int base = idx * 4;
        float vals[4] = {wv.x, wv.y, wv.z, wv.w};
        #pragma unroll
        for (int j = 0; j < 4; j++) {
            __nv_bfloat16 h = __float2bfloat16_rn(vals[j]);
            sBh[base + j] = h;
            sBl[base + j] = __float2bfloat16_rn(vals[j] - __bfloat162float(h));
        }
    }
    if (BIAS) {
        for (int c = tid; c < M; c += THREADS) sBias[c] = bias[c];
    }

    const float4* in4 = (const float4*)in;
    int ntiles = (n + RT - 1) / RT;
    for (int t = blockIdx.x; t < ntiles; t += gridDim.x) {
        int row0 = t * RT;
        __syncthreads();   // sOut free (epilogue of prev tile done), sA free
        // Stage A hi/lo
        for (int idx = tid; idx < RT * KV; idx += THREADS) {
            int r = idx / KV, k4 = idx % KV;
            int grow = row0 + r;
            float4 v = (grow < n) ? in4[(size_t)grow * KV + k4]
                                  : make_float4(0.f, 0.f, 0.f, 0.f);
            int base = r * SA + k4 * 4;
            float vals[4] = {v.x, v.y, v.z, v.w};
            #pragma unroll
            for (int j = 0; j < 4; j++) {
                __nv_bfloat16 h = __float2bfloat16_rn(vals[j]);
                sAh[base + j] = h;
                sAl[base + j] = __float2bfloat16_rn(vals[j] - __bfloat162float(h));
            }
        }
        __syncthreads();

        // MMA
        #pragma unroll
        for (int tt = 0; tt < TPW; tt++) {
            int tile = wid * TPW + tt;
            int rt = tile / CT, ct = tile % CT;
            wmma::fragment<wmma::accumulator, 16, 16, 16, float> acc;
            wmma::fill_fragment(acc, 0.0f);
            #pragma unroll
            for (int kf = 0; kf < KT; kf++) {
                wmma::fragment<wmma::matrix_a, 16, 16, 16, __nv_bfloat16, wmma::row_major> ah, al;
                wmma::fragment<wmma::matrix_b, 16, 16, 16, __nv_bfloat16, wmma::row_major> bh, bl;
                const __nv_bfloat16* pa = sAh + rt * 16 * SA + kf * 16;
                const __nv_bfloat16* pb = sBh + kf * 16 * M + ct * 16;
                wmma::load_matrix_sync(ah, pa, SA);
                wmma::load_matrix_sync(al, sAl + (pa - sAh), SA);
                wmma::load_matrix_sync(bh, pb, M);
                wmma::load_matrix_sync(bl, sBl + (pb - sBh), M);
                wmma::mma_sync(acc, ah, bh, acc);
                wmma::mma_sync(acc, ah, bl, acc);
                wmma::mma_sync(acc, al, bh, acc);
            }
            wmma::store_matrix_sync(sOut + rt * 16 * M + ct * 16, acc, M, wmma::mem_row_major);
        }
        __syncthreads();

        // Epilogue
        for (int idx = tid; idx < RT * (M / 4); idx += THREADS) {
            int r = idx / (M / 4), c4 = idx % (M / 4);
            int row = row0 + r;
            if (row < n) {
                float4 v = *(const float4*)&sOut[r * M + c4 * 4];
                if (BIAS) {
                    const float* bp = sBias + c4 * 4;
                    v.x += bp[0]; v.y += bp[1]; v.z += bp[2]; v.w += bp[3];
                }
                if (RSCALE) {
                    float rs = g_norm_out[row];
                    v.x *= rs; v.y *= rs; v.z *= rs; v.w *= rs;
                }
                if (RELU) {
                    v.x = fmaxf(v.x, 0.f); v.y = fmaxf(v.y, 0.f);
                    v.z = fmaxf(v.z, 0.f); v.w = fmaxf(v.w, 0.f);
                }
                *(float4*)&out[(size_t)row * M + c4 * 4] = v;
            }
        }
    }
}

// ---------------------------------------------------------------------------
// Register-tiled fp32 GEMM (R12 verbatim) — used for gemm3 (64->32).
// ---------------------------------------------------------------------------
template<int K, int M, int R, bool RELU, bool BIAS, bool RSCALE, int MAXB>
__global__ void __launch_bounds__(256, MAXB)
gemm_kernel(const float* __restrict__ in, const float* __restrict__ W,
            const float* __restrict__ bias, float* __restrict__ out, int n) {
    constexpr int THREADS = 256;
    constexpr int CGT = M / 4;
    constexpr int RPAR = THREADS / CGT;
    constexpr int RTILE = RPAR * R;
    constexpr int KV = K / 4;
    constexpr int KP = K + 4;

    extern __shared__ char smx[];
    float4* sW4 = (float4*)smx;
    float*  sIn = (float*)(smx + (size_t)K * CGT * 16);

    const int tid = threadIdx.x;
    for (int idx = tid; idx < K * CGT; idx += THREADS)
        sW4[idx] = ((const float4*)W)[idx];

    int cg = tid % CGT;
    int rg = tid / CGT;
    int c0 = cg * 4;

    float4 bv = make_float4(0.f, 0.f, 0.f, 0.f);
    if (BIAS) bv = *(const float4*)&bias[c0];

    const float4* in4 = (const float4*)in;
    int ntiles = (n + RTILE - 1) / RTILE;
    for (int t = blockIdx.x; t < ntiles; t += gridDim.x) {
        int row0 = t * RTILE;
        __syncthreads();
        for (int idx = tid; idx < RTILE * KV; idx += THREADS) {
            int r = idx / KV, k4 = idx % KV;
            int row = row0 + r;
            float4 v = (row < n) ? in4[(size_t)row * KV + k4]
                                 : make_float4(0.f, 0.f, 0.f, 0.f);
            *(float4*)&sIn[r * KP + k4 * 4] = v;
        }
        __syncthreads();

        float4 acc[R];
        #pragma unroll
        for (int r = 0; r < R; r++) acc[r] = make_float4(0.f, 0.f, 0.f, 0.f);

        #pragma unroll 2
        for (int k4 = 0; k4 < KV; k4++) {
            float4 w0 = sW4[(k4 * 4 + 0) * CGT + cg];
            float4 w1 = sW4[(k4 * 4 + 1) * CGT + cg];
            float4 w2 = sW4[(k4 * 4 + 2) * CGT + cg];
            float4 w3 = sW4[(k4 * 4 + 3) * CGT + cg];
            #pragma unroll
            for (int r = 0; r < R; r++) {
                float4 x = *(const float4*)&sIn[(rg + r * RPAR) * KP + k4 * 4];
                acc[r].x = fmaf(x.x, w0.x, fmaf(x.y, w1.x, fmaf(x.z, w2.x, fmaf(x.w, w3.x, acc[r].x))));
                acc[r].y = fmaf(x.x, w0.y, fmaf(x.y, w1.y, fmaf(x.z, w2.y, fmaf(x.w, w3.y, acc[r].y))));
                acc[r].z = fmaf(x.x, w0.z, fmaf(x.y, w1.z, fmaf(x.z, w2.z, fmaf(x.w, w3.z, acc[r].z))));
                acc[r].w = fmaf(x.x, w0.w, fmaf(x.y, w1.w, fmaf(x.z, w2.w, fmaf(x.w, w3.w, acc[r].w))));
            }
        }

        #pragma unroll
        for (int r = 0; r < R; r++) {
            int row = row0 + rg + r * RPAR;
            if (row < n) {
                float4 v = acc[r];
                if (BIAS) { v.x += bv.x; v.y += bv.y; v.z += bv.z; v.w += bv.w; }
                if (RSCALE) {
                    float rsc = g_norm_out[row];
                    v.x *= rsc; v.y *= rsc; v.z *= rsc; v.w *= rsc;
                }
                if (RELU) {
                    v.x = fmaxf(v.x, 0.f); v.y = fmaxf(v.y, 0.f);
                    v.z = fmaxf(v.z, 0.f); v.w = fmaxf(v.w, 0.f);
                }
                *(float4*)&out[(size_t)row * M + c0] = v;
            }
        }
    }
}

// ---------------------------------------------------------------------------
// Fused: agg(h,32) *norm_in +b3, relu -> @W4[32,4] -> *norm_out (R12 verbatim)
// ---------------------------------------------------------------------------
__global__ void agg32_gemm4(const float* __restrict__ hin,
                            const float* __restrict__ W4,
                            const float* __restrict__ b3,
                            float* __restrict__ hout, int n) {
    int warp = (blockIdx.x * blockDim.x + threadIdx.x) >> 5;
    int lane = threadIdx.x & 31;
    if (warp >= n) return;
    int node = warp;
    float4 w4 = *(const float4*)&W4[lane * 4];
    float bl = b3[lane];
    int beg = g_row_ptr[node], end = g_row_ptr[node + 1];
    const float* base = hin + lane;
    float a0 = 0, a1 = 0, a2 = 0, a3 = 0;
    float a4 = 0, a5 = 0, a6 = 0, a7 = 0;
    int e = beg;
    for (; e + 7 < end; e += 8) {
        a0 += base[g_csr_src[e] * 32];
        a1 += base[g_csr_src[e + 1] * 32];
        a2 += base[g_csr_src[e + 2] * 32];
        a3 += base[g_csr_src[e + 3] * 32];
        a4 += base[g_csr_src[e + 4] * 32];
        a5 += base[g_csr_src[e + 5] * 32];
        a6 += base[g_csr_src[e + 6] * 32];
        a7 += base[g_csr_src[e + 7] * 32];
    }
    for (; e < end; e++) a0 += base[g_csr_src[e] * 32];
    float a = ((a0 + a1) + (a2 + a3)) + ((a4 + a5) + (a6 + a7));
    a = fmaxf(fmaf(a, g_norm_in[node], bl), 0.0f);
    float4 y;
    y.x = a * w4.x; y.y = a * w4.y; y.z = a * w4.z; y.w = a * w4.w;
    #pragma unroll
    for (int o = 16; o; o >>= 1) {
        y.x += __shfl_xor_sync(0xffffffffu, y.x, o);
        y.y += __shfl_xor_sync(0xffffffffu, y.y, o);
        y.z += __shfl_xor_sync(0xffffffffu, y.z, o);
        y.w += __shfl_xor_sync(0xffffffffu, y.w, o);
    }
    if (lane == 0) {
        float s = g_norm_out[node];
        y.x *= s; y.y *= s; y.z *= s; y.w *= s;
        *(float4*)&hout[(size_t)node * 4] = y;
    }
}

// ---------------------------------------------------------------------------
// Final: agg(h,4) * norm_in + b4 -> per-graph atomic sum (R12 verbatim).
// ---------------------------------------------------------------------------
__global__ void agg4_readout(const float* __restrict__ hin,
                             const float* __restrict__ b4,
                             const int* __restrict__ gid, int n) {
    int warp = (blockIdx.x * blockDim.x + threadIdx.x) >> 5;
    int lane = threadIdx.x & 31;
    int node = warp * 8 + (lane >> 2);
    int l = lane & 3;
    float v = 0.f;
    int g = 0;
    bool valid = node < n;
    if (valid) {
        int beg = g_row_ptr[node], end = g_row_ptr[node + 1];
        float a0 = 0, a1 = 0, a2 = 0, a3 = 0;
        int e = beg;
        for (; e + 3 < end; e += 4) {
            a0 += hin[g_csr_src[e] * 4 + l];
            a1 += hin[g_csr_src[e + 1] * 4 + l];
            a2 += hin[g_csr_src[e + 2] * 4 + l];
            a3 += hin[g_csr_src[e + 3] * 4 + l];
        }
        for (; e < end; e++) a0 += hin[g_csr_src[e] * 4 + l];
        v = fmaf(((a0 + a1) + (a2 + a3)), g_norm_in[node], b4[l]);
        g = gid[node];
    }
    unsigned act = __ballot_sync(0xffffffffu, valid);
    if (act == 0xffffffffu) {
        int g0 = __shfl_sync(0xffffffffu, g, 0);
        if (__all_sync(0xffffffffu, g == g0)) {
            v += __shfl_xor_sync(0xffffffffu, v, 4);
            v += __shfl_xor_sync(0xffffffffu, v, 8);
            v += __shfl_xor_sync(0xffffffffu, v, 16);
            if (lane < 4) atomicAdd(&g_gsum[g0 * 4 + lane], v);
            return;
        }
    }
    if (valid) atomicAdd(&g_gsum[g * 4 + l], v);
}

// Per-graph mean; counts via binary search over sorted gid.
__global__ void graph_mean_kernel(float* __restrict__ out,
                                  const int* __restrict__ gid, int n, int g) {
    int i = blockIdx.x * blockDim.x + threadIdx.x;
    if (i >= g) return;
    int lo = 0, hi = n;
    while (lo < hi) { int mid = (lo + hi) >> 1; if (gid[mid] < i) lo = mid + 1; else hi = mid; }
    int lo2 = lo, hi2 = n;
    while (lo2 < hi2) { int mid = (lo2 + hi2) >> 1; if (gid[mid] < i + 1) lo2 = mid + 1; else hi2 = mid; }
    float c = fmaxf((float)(lo2 - lo), 1.0f);
    float4 sres = *(const float4*)&g_gsum[i * 4];
    out[i * 4 + 0] = sres.x / c;
    out[i * 4 + 1] = sres.y / c;
    out[i * 4 + 2] = sres.z / c;
    out[i * 4 + 3] = sres.w / c;
}

// ---------------------------------------------------------------------------
extern "C" void kernel_launch(void* const* d_in, const int* in_sizes, int n_in,
                              void* d_out, int out_size) {
    const float* x  = (const float*)d_in[0];
    const float* W1 = (const float*)d_in[1];
    const float* b1 = (const float*)d_in[2];
    const float* W2 = (const float*)d_in[3];
    const float* b2 = (const float*)d_in[4];
    const float* W3 = (const float*)d_in[5];
    const float* b3 = (const float*)d_in[6];
    const float* W4 = (const float*)d_in[7];
    const float* b4 = (const float*)d_in[8];
    const int* src = (const int*)d_in[9];
    const int* dst = (const int*)d_in[10];
    const int* gid = (const int*)d_in[11];
    float* out = (float*)d_out;

    int n = in_sizes[0] / 64;
    int e = in_sizes[9];
    int g = out_size / 4;
    int nsb = (n + 4095) / 4096;

    float *h0, *h1;
    void *p_dego, *p_degi, *p_gsum, *p_sync;
    cudaGetSymbolAddress((void**)&h0, g_h0);
    cudaGetSymbolAddress((void**)&h1, g_h1);
    cudaGetSymbolAddress(&p_dego, g_deg_out);
    cudaGetSymbolAddress(&p_degi, g_deg_in);
    cudaGetSymbolAddress(&p_gsum, g_gsum);
    cudaGetSymbolAddress(&p_sync, g_sync);

    const int T = 256;
    auto blocks = [](int work, int t) { return (work + t - 1) / t; };
    auto warp_grid = [&](int nodes_per_warp) {
        int warps = (n + nodes_per_warp - 1) / nodes_per_warp;
        return (warps * 32 + T - 1) / T;
    };

    // wmma GEMM smem: sA(hi+lo) RT*(K+8)*2B*2 + sB(hi+lo) K*M*2B*2 + sOut RT*M*4 + bias M*4
    const int SMW1 = 2 * 64 * 72 * 2 + 2 * 64 * 128 * 2 + 64 * 128 * 4 + 128 * 4;  // 84.5K
    const int SMW2 = 2 * 64 * 136 * 2 + 2 * 128 * 64 * 2 + 64 * 64 * 4 + 64 * 4;   // 84.2K
    const int SM3  = 64 * 8 * 16 + 256 * 68 * 4;
    cudaFuncSetAttribute((const void*)gemm_wmma_kernel<64, 128, true, true, false>,
                         cudaFuncAttributeMaxDynamicSharedMemorySize, SMW1);
    cudaFuncSetAttribute((const void*)gemm_wmma_kernel<128, 64, false, false, true>,
                         cudaFuncAttributeMaxDynamicSharedMemorySize, SMW2);
    cudaFuncSetAttribute((const void*)gemm_kernel<64, 32, 8, false, false, true, 2>,
                         cudaFuncAttributeMaxDynamicSharedMemorySize, SM3);

    // Zeroing via memset nodes (not kernel launches)
    cudaMemsetAsync(p_dego, 0, (size_t)n * 4);
    cudaMemsetAsync(p_degi, 0, (size_t)n * 4);
    cudaMemsetAsync(p_gsum, 0, (size_t)g * 4 * 4);
    cudaMemsetAsync(p_sync, 0, 4 * 4);

    // Launch 1: fused preprocessing
    prep_kernel<<<148, 1024>>>(src, dst, n, e, nsb);

    // Launch 2: agg(x * norm_out) -> *norm_in
    agg64_kernel<false, false, true><<<warp_grid(1), T>>>(x, h1, nullptr, n);
    // Launch 3: @W1 + b1, relu  (wmma bf16x3)
    gemm_wmma_kernel<64, 128, true, true, false><<<296, T, SMW1>>>(h1, W1, b1, h0, n);
    // Launch 4 (profiled): @W2, *norm_out  (wmma bf16x3)
    gemm_wmma_kernel<128, 64, false, false, true><<<296, T, SMW2>>>(h0, W2, nullptr, h1, n);
    // Launch 5: agg -> *norm_in + b2, relu
    agg64_kernel<true, true, false><<<warp_grid(1), T>>>(h1, h0, b2, n);
    // Launch 6: @W3, *norm_out  (fp32 register-tiled)
    gemm_kernel<64, 32, 8, false, false, true, 2><<<296, T, SM3>>>(h0, W3, nullptr, h1, n);
    // Launch 7: agg32 -> +b3, relu -> @W4 -> *norm_out
    agg32_gemm4<<<warp_grid(1), T>>>(h1, W4, b3, h0, n);
    // Launch 8: agg4 + readout
    agg4_readout<<<warp_grid(8), T>>>(h0, b4, gid, n);
    // Launch 9: per-graph mean
    graph_mean_kernel<<<blocks(g, T), T>>>(out, gid, n, g);
}

// round 16
// speedup vs baseline: 1.2945x; 1.2945x over previous
#include <cuda_runtime.h>

// ---------------------------------------------------------------------------
// GCN 4-layer forward on GB300 (sm_103a).
// R15: R12 skeleton + GEMM occupancy fix: __launch_bounds__(256,3) caps regs
// at ~84, R=4 for gemm2/gemm3 (smaller acc + smem) -> 3 blocks/SM, 24 warps.
// R12 profile showed gemm2 at occ 22% / fma 36% (occupancy-starved, not
// resource-bound). Tensor paths abandoned: tcgen05 won't compile (sm_103
// target), wmma measured fragment-load-bound (86us, tensor 9.4%).
// ---------------------------------------------------------------------------

#define MAX_N 100000
#define MAX_E 800000
#define MAX_G 500

__device__ float g_norm_out[MAX_N];
__device__ float g_norm_in[MAX_N];
__device__ int   g_deg_out[MAX_N];
__device__ int   g_deg_in[MAX_N];
__device__ int   g_row_ptr[MAX_N + 1];
__device__ int   g_cursor[MAX_N];
__device__ int   g_csr_src[MAX_E];
__device__ float g_h0[MAX_N * 128];
__device__ float g_h1[MAX_N * 64];
__device__ float g_gsum[MAX_G * 4];
__device__ int   g_bsum[32];
__device__ int   g_sync[4];

// Device-wide barrier: all blocks co-resident (148 blocks, 1/SM).
__device__ __forceinline__ void gbar(int idx, int nb) {
    __syncthreads();
    if (threadIdx.x == 0) {
        __threadfence();
        atomicAdd(&g_sync[idx], 1);
        while (atomicAdd(&g_sync[idx], 0) < nb) { }
    }
    __syncthreads();
}

// ---------------------------------------------------------------------------
// Persistent preprocessing: degrees -> scan(+norms) -> csr_fill.
// ---------------------------------------------------------------------------
__global__ void __launch_bounds__(1024, 1)
prep_kernel(const int* __restrict__ src, const int* __restrict__ dst,
            int n, int e, int nsb) {
    const int NBK = gridDim.x;
    int b = blockIdx.x, t = threadIdx.x, lane = t & 31, w = t >> 5;
    int gtid = b * 1024 + t;
    int gsz = NBK * 1024;

    for (int i = gtid; i < e; i += gsz) {
        atomicAdd(&g_deg_out[src[i]], 1);
        atomicAdd(&g_deg_in[dst[i]], 1);
    }
    gbar(0, NBK);

    __shared__ int swarp[32];
    __shared__ int s_boff;
    int4 v = make_int4(0, 0, 0, 0);
    int s = 0, ts = 0;
    int i0 = b * 4096 + t * 4;
    if (b < nsb) {
        if (i0 + 3 < n) v = *(const int4*)&g_deg_in[i0];
        else {
            if (i0     < n) v.x = g_deg_in[i0];
            if (i0 + 1 < n) v.y = g_deg_in[i0 + 1];
            if (i0 + 2 < n) v.z = g_deg_in[i0 + 2];
            if (i0 + 3 < n) v.w = g_deg_in[i0 + 3];
        }
        if (i0 < n) {
            g_norm_in[i0] = rsqrtf(fmaxf((float)v.x, 1.f));
            g_norm_out[i0] = rsqrtf(fmaxf((float)g_deg_out[i0], 1.f));
        }
        if (i0 + 1 < n) {
            g_norm_in[i0 + 1] = rsqrtf(fmaxf((float)v.y, 1.f));
            g_norm_out[i0 + 1] = rsqrtf(fmaxf((float)g_deg_out[i0 + 1], 1.f));
        }
        if (i0 + 2 < n) {
            g_norm_in[i0 + 2] = rsqrtf(fmaxf((float)v.z, 1.f));
            g_norm_out[i0 + 2] = rsqrtf(fmaxf((float)g_deg_out[i0 + 2], 1.f));
        }
        if (i0 + 3 < n) {
            g_norm_in[i0 + 3] = rsqrtf(fmaxf((float)v.w, 1.f));
            g_norm_out[i0 + 3] = rsqrtf(fmaxf((float)g_deg_out[i0 + 3], 1.f));
        }
        ts = v.x + v.y + v.z + v.w;
        s = ts;
        #pragma unroll
        for (int o = 1; o < 32; o <<= 1) {
            int x = __shfl_up_sync(0xffffffffu, s, o);
            if (lane >= o) s += x;
        }
        if (lane == 31) swarp[w] = s;
        __syncthreads();
        if (w == 0) {
            int ws = swarp[lane];
            #pragma unroll
            for (int o = 1; o < 32; o <<= 1) {
                int x = __shfl_up_sync(0xffffffffu, ws, o);
                if (lane >= o) ws += x;
            }
            swarp[lane] = ws;
        }
        __syncthreads();
        if (t == 0) g_bsum[b] = swarp[31];
    }
    gbar(1, NBK);

    if (b < nsb) {
        if (w == 0) {
            int acc = (lane < b) ? g_bsum[lane] : 0;
            #pragma unroll
            for (int o = 16; o; o >>= 1) acc += __shfl_down_sync(0xffffffffu, acc, o);
            if (lane == 0) {
                s_boff = acc;
                if (b == nsb - 1) g_row_ptr[n] = acc + swarp[31];
            }
        }
        __syncthreads();
        int pre = (w > 0) ? swarp[w - 1] : 0;
        int e0 = s_boff + pre + s - ts;
        int e1 = e0 + v.x, e2 = e1 + v.y, e3 = e2 + v.z;
        if (i0     < n) { g_row_ptr[i0]     = e0; g_cursor[i0]     = e0; }
        if (i0 + 1 < n) { g_row_ptr[i0 + 1] = e1; g_cursor[i0 + 1] = e1; }
        if (i0 + 2 < n) { g_row_ptr[i0 + 2] = e2; g_cursor[i0 + 2] = e2; }
        if (i0 + 3 < n) { g_row_ptr[i0 + 3] = e3; g_cursor[i0 + 3] = e3; }
    }
    gbar(2, NBK);

    for (int i = gtid; i < e; i += gsz) {
        int p = atomicAdd(&g_cursor[dst[i]], 1);
        g_csr_src[p] = src[i];
    }
}

// ---------------------------------------------------------------------------
// Gather-aggregate DIM=64: warp/node, 8-way MLP unroll.
// ---------------------------------------------------------------------------
template<bool RELU, bool HASB, bool SRCSCALE>
__global__ void agg64_kernel(const float* __restrict__ hin,
                             float* __restrict__ hout,
                             const float* __restrict__ bias, int n) {
    int node = (blockIdx.x * blockDim.x + threadIdx.x) >> 5;
    int l = threadIdx.x & 31;
    if (node >= n) return;
    int beg = g_row_ptr[node];
    int end = g_row_ptr[node + 1];
    float ni = g_norm_in[node];
    const float* base = hin + l * 2;
    float2 a0 = {0,0}, a1 = {0,0}, a2 = {0,0}, a3 = {0,0};
    float2 a4 = {0,0}, a5 = {0,0}, a6 = {0,0}, a7 = {0,0};
    int e = beg;
    for (; e + 7 < end; e += 8) {
        int s0 = g_csr_src[e],     s1 = g_csr_src[e + 1];
        int s2 = g_csr_src[e + 2], s3 = g_csr_src[e + 3];
        int s4 = g_csr_src[e + 4], s5 = g_csr_src[e + 5];
        int s6 = g_csr_src[e + 6], s7 = g_csr_src[e + 7];
        float2 v0 = *(const float2*)(base + s0 * 64);
        float2 v1 = *(const float2*)(base + s1 * 64);
        float2 v2 = *(const float2*)(base + s2 * 64);
        float2 v3 = *(const float2*)(base + s3 * 64);
        float2 v4 = *(const float2*)(base + s4 * 64);
        float2 v5 = *(const float2*)(base + s5 * 64);
        float2 v6 = *(const float2*)(base + s6 * 64);
        float2 v7 = *(const float2*)(base + s7 * 64);
        if (SRCSCALE) {
            float n0 = g_norm_out[s0], n1 = g_norm_out[s1];
            float n2 = g_norm_out[s2], n3 = g_norm_out[s3];
            float n4 = g_norm_out[s4], n5 = g_norm_out[s5];
            float n6 = g_norm_out[s6], n7 = g_norm_out[s7];
            a0.x = fmaf(v0.x, n0, a0.x); a0.y = fmaf(v0.y, n0, a0.y);
            a1.x = fmaf(v1.x, n1, a1.x); a1.y = fmaf(v1.y, n1, a1.y);
            a2.x = fmaf(v2.x, n2, a2.x); a2.y = fmaf(v2.y, n2, a2.y);
            a3.x = fmaf(v3.x, n3, a3.x); a3.y = fmaf(v3.y, n3, a3.y);
            a4.x = fmaf(v4.x, n4, a4.x); a4.y = fmaf(v4.y, n4, a4.y);
            a5.x = fmaf(v5.x, n5, a5.x); a5.y = fmaf(v5.y, n5, a5.y);
            a6.x = fmaf(v6.x, n6, a6.x); a6.y = fmaf(v6.y, n6, a6.y);
            a7.x = fmaf(v7.x, n7, a7.x); a7.y = fmaf(v7.y, n7, a7.y);
        } else {
            a0.x += v0.x; a0.y += v0.y; a1.x += v1.x; a1.y += v1.y;
            a2.x += v2.x; a2.y += v2.y; a3.x += v3.x; a3.y += v3.y;
            a4.x += v4.x; a4.y += v4.y; a5.x += v5.x; a5.y += v5.y;
            a6.x += v6.x; a6.y += v6.y; a7.x += v7.x; a7.y += v7.y;
        }
    }
    for (; e < end; e++) {
        int s0 = g_csr_src[e];
        float2 v = *(const float2*)(base + s0 * 64);
        if (SRCSCALE) {
            float n0 = g_norm_out[s0];
            a0.x = fmaf(v.x, n0, a0.x); a0.y = fmaf(v.y, n0, a0.y);
        } else { a0.x += v.x; a0.y += v.y; }
    }
    float ax = ((a0.x + a1.x) + (a2.x + a3.x)) + ((a4.x + a5.x) + (a6.x + a7.x));
    float ay = ((a0.y + a1.y) + (a2.y + a3.y)) + ((a4.y + a5.y) + (a6.y + a7.y));
    ax *= ni; ay *= ni;
    if (HASB) { ax += bias[l * 2]; ay += bias[l * 2 + 1]; }
    if (RELU) { ax = fmaxf(ax, 0.0f); ay = fmaxf(ay, 0.0f); }
    float2 o; o.x = ax; o.y = ay;
    *(float2*)&hout[node * 64 + l * 2] = o;
}

// ---------------------------------------------------------------------------
// Register-tiled GEMM (R12 design, occupancy-tuned): 4 cols x R rows/thread.
// __launch_bounds__(256, MAXB) with MAXB=3 caps regs ~84 -> 3 blocks/SM.
// ---------------------------------------------------------------------------
template<int K, int M, int R, bool RELU, bool BIAS, bool RSCALE, int MAXB>
__global__ void __launch_bounds__(256, MAXB)
gemm_kernel(const float* __restrict__ in, const float* __restrict__ W,
            const float* __restrict__ bias, float* __restrict__ out, int n) {
    constexpr int THREADS = 256;
    constexpr int CGT = M / 4;
    constexpr int RPAR = THREADS / CGT;
    constexpr int RTILE = RPAR * R;
    constexpr int KV = K / 4;
    constexpr int KP = K + 4;

    extern __shared__ char smx[];
    float4* sW4 = (float4*)smx;                         // K*CGT float4
    float*  sIn = (float*)(smx + (size_t)K * CGT * 16); // RTILE*KP floats

    const int tid = threadIdx.x;
    for (int idx = tid; idx < K * CGT; idx += THREADS)
        sW4[idx] = ((const float4*)W)[idx];

    int cg = tid % CGT;
    int rg = tid / CGT;
    int c0 = cg * 4;

    float4 bv = make_float4(0.f, 0.f, 0.f, 0.f);
    if (BIAS) bv = *(const float4*)&bias[c0];

    const float4* in4 = (const float4*)in;
    int ntiles = (n + RTILE - 1) / RTILE;
    for (int t = blockIdx.x; t < ntiles; t += gridDim.x) {
        int row0 = t * RTILE;
        __syncthreads();
        for (int idx = tid; idx < RTILE * KV; idx += THREADS) {
            int r = idx / KV, k4 = idx % KV;
            int row = row0 + r;
            float4 v = (row < n) ? in4[(size_t)row * KV + k4]
                                 : make_float4(0.f, 0.f, 0.f, 0.f);
            *(float4*)&sIn[r * KP + k4 * 4] = v;
        }
        __syncthreads();

        float4 acc[R];
        #pragma unroll
        for (int r = 0; r < R; r++) acc[r] = make_float4(0.f, 0.f, 0.f, 0.f);

        #pragma unroll 2
        for (int k4 = 0; k4 < KV; k4++) {
            float4 w0 = sW4[(k4 * 4 + 0) * CGT + cg];
            float4 w1 = sW4[(k4 * 4 + 1) * CGT + cg];
            float4 w2 = sW4[(k4 * 4 + 2) * CGT + cg];
            float4 w3 = sW4[(k4 * 4 + 3) * CGT + cg];
            #pragma unroll
            for (int r = 0; r < R; r++) {
                float4 x = *(const float4*)&sIn[(rg + r * RPAR) * KP + k4 * 4];
                acc[r].x = fmaf(x.x, w0.x, fmaf(x.y, w1.x, fmaf(x.z, w2.x, fmaf(x.w, w3.x, acc[r].x))));
                acc[r].y = fmaf(x.x, w0.y, fmaf(x.y, w1.y, fmaf(x.z, w2.y, fmaf(x.w, w3.y, acc[r].y))));
                acc[r].z = fmaf(x.x, w0.z, fmaf(x.y, w1.z, fmaf(x.z, w2.z, fmaf(x.w, w3.z, acc[r].z))));
                acc[r].w = fmaf(x.x, w0.w, fmaf(x.y, w1.w, fmaf(x.z, w2.w, fmaf(x.w, w3.w, acc[r].w))));
            }
        }

        #pragma unroll
        for (int r = 0; r < R; r++) {
            int row = row0 + rg + r * RPAR;
            if (row < n) {
                float4 v = acc[r];
                if (BIAS) { v.x += bv.x; v.y += bv.y; v.z += bv.z; v.w += bv.w; }
                if (RSCALE) {
                    float rs = g_norm_out[row];
                    v.x *= rs; v.y *= rs; v.z *= rs; v.w *= rs;
                }
                if (RELU) {
                    v.x = fmaxf(v.x, 0.f); v.y = fmaxf(v.y, 0.f);
                    v.z = fmaxf(v.z, 0.f); v.w = fmaxf(v.w, 0.f);
                }
                *(float4*)&out[(size_t)row * M + c0] = v;
            }
        }
    }
}

// ---------------------------------------------------------------------------
// Fused: agg(h,32) *norm_in +b3, relu -> @W4[32,4] -> *norm_out
// ---------------------------------------------------------------------------
__global__ void agg32_gemm4(const float* __restrict__ hin,
                            const float* __restrict__ W4,
                            const float* __restrict__ b3,
                            float* __restrict__ hout, int n) {
    int warp = (blockIdx.x * blockDim.x + threadIdx.x) >> 5;
    int lane = threadIdx.x & 31;
    if (warp >= n) return;
    int node = warp;
    float4 w4 = *(const float4*)&W4[lane * 4];
    float bl = b3[lane];
    int beg = g_row_ptr[node], end = g_row_ptr[node + 1];
    const float* base = hin + lane;
    float a0 = 0, a1 = 0, a2 = 0, a3 = 0;
    float a4 = 0, a5 = 0, a6 = 0, a7 = 0;
    int e = beg;
    for (; e + 7 < end; e += 8) {
        a0 += base[g_csr_src[e] * 32];
        a1 += base[g_csr_src[e + 1] * 32];
        a2 += base[g_csr_src[e + 2] * 32];
        a3 += base[g_csr_src[e + 3] * 32];
        a4 += base[g_csr_src[e + 4] * 32];
        a5 += base[g_csr_src[e + 5] * 32];
        a6 += base[g_csr_src[e + 6] * 32];
        a7 += base[g_csr_src[e + 7] * 32];
    }
    for (; e < end; e++) a0 += base[g_csr_src[e] * 32];
    float a = ((a0 + a1) + (a2 + a3)) + ((a4 + a5) + (a6 + a7));
    a = fmaxf(fmaf(a, g_norm_in[node], bl), 0.0f);
    float4 y;
    y.x = a * w4.x; y.y = a * w4.y; y.z = a * w4.z; y.w = a * w4.w;
    #pragma unroll
    for (int o = 16; o; o >>= 1) {
        y.x += __shfl_xor_sync(0xffffffffu, y.x, o);
        y.y += __shfl_xor_sync(0xffffffffu, y.y, o);
        y.z += __shfl_xor_sync(0xffffffffu, y.z, o);
        y.w += __shfl_xor_sync(0xffffffffu, y.w, o);
    }
    if (lane == 0) {
        float s = g_norm_out[node];
        y.x *= s; y.y *= s; y.z *= s; y.w *= s;
        *(float4*)&hout[(size_t)node * 4] = y;
    }
}

// ---------------------------------------------------------------------------
// Final: agg(h,4) * norm_in + b4 -> per-graph atomic sum.
// ---------------------------------------------------------------------------
__global__ void agg4_readout(const float* __restrict__ hin,
                             const float* __restrict__ b4,
                             const int* __restrict__ gid, int n) {
    int warp = (blockIdx.x * blockDim.x + threadIdx.x) >> 5;
    int lane = threadIdx.x & 31;
    int node = warp * 8 + (lane >> 2);
    int l = lane & 3;
    float v = 0.f;
    int g = 0;
    bool valid = node < n;
    if (valid) {
        int beg = g_row_ptr[node], end = g_row_ptr[node + 1];
        float a0 = 0, a1 = 0, a2 = 0, a3 = 0;
        int e = beg;
        for (; e + 3 < end; e += 4) {
            a0 += hin[g_csr_src[e] * 4 + l];
            a1 += hin[g_csr_src[e + 1] * 4 + l];
            a2 += hin[g_csr_src[e + 2] * 4 + l];
            a3 += hin[g_csr_src[e + 3] * 4 + l];
        }
        for (; e < end; e++) a0 += hin[g_csr_src[e] * 4 + l];
        v = fmaf(((a0 + a1) + (a2 + a3)), g_norm_in[node], b4[l]);
        g = gid[node];
    }
    unsigned act = __ballot_sync(0xffffffffu, valid);
    if (act == 0xffffffffu) {
        int g0 = __shfl_sync(0xffffffffu, g, 0);
        if (__all_sync(0xffffffffu, g == g0)) {
            v += __shfl_xor_sync(0xffffffffu, v, 4);
            v += __shfl_xor_sync(0xffffffffu, v, 8);
            v += __shfl_xor_sync(0xffffffffu, v, 16);
            if (lane < 4) atomicAdd(&g_gsum[g0 * 4 + lane], v);
            return;
        }
    }
    if (valid) atomicAdd(&g_gsum[g * 4 + l], v);
}

// Per-graph mean; counts via binary search over sorted gid.
__global__ void graph_mean_kernel(float* __restrict__ out,
                                  const int* __restrict__ gid, int n, int g) {
    int i = blockIdx.x * blockDim.x + threadIdx.x;
    if (i >= g) return;
    int lo = 0, hi = n;
    while (lo < hi) { int mid = (lo + hi) >> 1; if (gid[mid] < i) lo = mid + 1; else hi = mid; }
    int lo2 = lo, hi2 = n;
    while (lo2 < hi2) { int mid = (lo2 + hi2) >> 1; if (gid[mid] < i + 1) lo2 = mid + 1; else hi2 = mid; }
    float c = fmaxf((float)(lo2 - lo), 1.0f);
    float4 sres = *(const float4*)&g_gsum[i * 4];
    out[i * 4 + 0] = sres.x / c;
    out[i * 4 + 1] = sres.y / c;
    out[i * 4 + 2] = sres.z / c;
    out[i * 4 + 3] = sres.w / c;
}

// ---------------------------------------------------------------------------
extern "C" void kernel_launch(void* const* d_in, const int* in_sizes, int n_in,
                              void* d_out, int out_size) {
    const float* x  = (const float*)d_in[0];
    const float* W1 = (const float*)d_in[1];
    const float* b1 = (const float*)d_in[2];
    const float* W2 = (const float*)d_in[3];
    const float* b2 = (const float*)d_in[4];
    const float* W3 = (const float*)d_in[5];
    const float* b3 = (const float*)d_in[6];
    const float* W4 = (const float*)d_in[7];
    const float* b4 = (const float*)d_in[8];
    const int* src = (const int*)d_in[9];
    const int* dst = (const int*)d_in[10];
    const int* gid = (const int*)d_in[11];
    float* out = (float*)d_out;

    int n = in_sizes[0] / 64;
    int e = in_sizes[9];
    int g = out_size / 4;
    int nsb = (n + 4095) / 4096;

    float *h0, *h1;
    void *p_dego, *p_degi, *p_gsum, *p_sync;
    cudaGetSymbolAddress((void**)&h0, g_h0);
    cudaGetSymbolAddress((void**)&h1, g_h1);
    cudaGetSymbolAddress(&p_dego, g_deg_out);
    cudaGetSymbolAddress(&p_degi, g_deg_in);
    cudaGetSymbolAddress(&p_gsum, g_gsum);
    cudaGetSymbolAddress(&p_sync, g_sync);

    const int T = 256;
    auto blocks = [](int work, int t) { return (work + t - 1) / t; };
    auto warp_grid = [&](int nodes_per_warp) {
        int warps = (n + nodes_per_warp - 1) / nodes_per_warp;
        return (warps * 32 + T - 1) / T;
    };

    // GEMM smem: sW4 = K*(M/4)*16B, sIn = RTILE*(K+4)*4B
    // gemm1 (64->128, R=8):  RTILE=64:  32768 + 64*68*4  = 50176  (3/SM ok)
    // gemm2 (128->64, R=4):  RTILE=64:  32768 + 64*132*4 = 66560  (3/SM ok)
    // gemm3 (64->32,  R=4):  RTILE=128: 8192  + 128*68*4 = 43008  (3/SM ok)
    const int SM1 = 64 * 32 * 16 + 64 * 68 * 4;
    const int SM2 = 128 * 16 * 16 + 64 * 132 * 4;
    const int SM3 = 64 * 8 * 16 + 128 * 68 * 4;
    cudaFuncSetAttribute((const void*)gemm_kernel<64, 128, 8, true, true, false, 3>,
                         cudaFuncAttributeMaxDynamicSharedMemorySize, SM1);
    cudaFuncSetAttribute((const void*)gemm_kernel<128, 64, 4, false, false, true, 3>,
                         cudaFuncAttributeMaxDynamicSharedMemorySize, SM2);
    cudaFuncSetAttribute((const void*)gemm_kernel<64, 32, 4, false, false, true, 3>,
                         cudaFuncAttributeMaxDynamicSharedMemorySize, SM3);

    // Zeroing via memset nodes (not kernel launches)
    cudaMemsetAsync(p_dego, 0, (size_t)n * 4);
    cudaMemsetAsync(p_degi, 0, (size_t)n * 4);
    cudaMemsetAsync(p_gsum, 0, (size_t)g * 4 * 4);
    cudaMemsetAsync(p_sync, 0, 4 * 4);

    // Launch 1: fused preprocessing
    prep_kernel<<<148, 1024>>>(src, dst, n, e, nsb);

    // Launch 2: agg(x * norm_out) -> *norm_in
    agg64_kernel<false, false, true><<<warp_grid(1), T>>>(x, h1, nullptr, n);
    // Launch 3: @W1 + b1, relu
    gemm_kernel<64, 128, 8, true, true, false, 3><<<444, T, SM1>>>(h1, W1, b1, h0, n);
    // Launch 4 (profiled): @W2, *norm_out
    gemm_kernel<128, 64, 4, false, false, true, 3><<<444, T, SM2>>>(h0, W2, nullptr, h1, n);
    // Launch 5: agg -> *norm_in + b2, relu
    agg64_kernel<true, true, false><<<warp_grid(1), T>>>(h1, h0, b2, n);
    // Launch 6: @W3, *norm_out
    gemm_kernel<64, 32, 4, false, false, true, 3><<<444, T, SM3>>>(h0, W3, nullptr, h1, n);
    // Launch 7: agg32 -> +b3, relu -> @W4 -> *norm_out
    agg32_gemm4<<<warp_grid(1), T>>>(h1, W4, b3, h0, n);
    // Launch 8: agg4 + readout
    agg4_readout<<<warp_grid(8), T>>>(h0, b4, gid, n);
    // Launch 9: per-graph mean
    graph_mean_kernel<<<blocks(g, T), T>>>(out, gid, n, g);
}